// round 6
// baseline (speedup 1.0000x reference)
#include <cuda_runtime.h>
#include <math.h>

// Problem constants (from reference)
#define NNODES 50000
#define NEDGES 800000
#define DIN    128
#define DOUT   128

// Scratch (static device arrays — no allocation allowed)
__device__ float g_z[(size_t)NNODES * DIN];   // 25.6 MB mixed aggregation buffer
__device__ float g_alpha[NNODES];

// ---------------------------------------------------------------------------
// Kernel 1: zero the z_mix scratch (float4 stores)
// ---------------------------------------------------------------------------
__global__ void zero_z_kernel() {
    const int total4 = NNODES * DIN / 4;  // 1.6M float4
    int i = blockIdx.x * blockDim.x + threadIdx.x;
    float4* p = reinterpret_cast<float4*>(g_z);
    if (i < total4) p[i] = make_float4(0.f, 0.f, 0.f, 0.f);
}

// ---------------------------------------------------------------------------
// Kernel 2: per-node gate alpha = sigmoid(x_i . theta + b). One warp per node.
// Writes both the scratch gate and the alpha output section.
// ---------------------------------------------------------------------------
__global__ void alpha_kernel(const float* __restrict__ x,
                             const float* __restrict__ aw,
                             const float* __restrict__ ab,
                             float* __restrict__ alpha_out) {
    int warp = (blockIdx.x * blockDim.x + threadIdx.x) >> 5;
    int lane = threadIdx.x & 31;
    if (warp >= NNODES) return;
    float4 xv = reinterpret_cast<const float4*>(x + (size_t)warp * DIN)[lane];
    float4 wv = reinterpret_cast<const float4*>(aw)[lane];
    float s = xv.x * wv.x + xv.y * wv.y + xv.z * wv.z + xv.w * wv.w;
    #pragma unroll
    for (int o = 16; o > 0; o >>= 1) s += __shfl_xor_sync(0xffffffffu, s, o);
    if (lane == 0) {
        float a = 1.0f / (1.0f + expf(-(s + ab[0])));
        g_alpha[warp]   = a;
        alpha_out[warp] = a;
    }
}

// ---------------------------------------------------------------------------
// Kernel 3: fused gated scatter. One warp per edge-slot; slots [0,E) are the
// low-pass edges (weight = alpha[row]*val), slots [E,2E) high-pass
// (weight = (1-alpha[row])*val). Each lane handles 4 features (float4 gather,
// 4 scalar atomicAdds into z_mix[row]).
// ---------------------------------------------------------------------------
__global__ void scatter_kernel(const float* __restrict__ x,
                               const int*  __restrict__ lpr, const int* __restrict__ lpc,
                               const float* __restrict__ lpv,
                               const int*  __restrict__ hpr, const int* __restrict__ hpc,
                               const float* __restrict__ hpv) {
    int gw   = blockIdx.x * (blockDim.x >> 5) + (threadIdx.x >> 5);
    int lane = threadIdx.x & 31;
    if (gw >= 2 * NEDGES) return;

    int row, col;
    float w;
    if (gw < NEDGES) {
        row = lpr[gw]; col = lpc[gw];
        w = g_alpha[row] * lpv[gw];
    } else {
        int e = gw - NEDGES;
        row = hpr[e]; col = hpc[e];
        w = (1.0f - g_alpha[row]) * hpv[e];
    }

    float4 xv = reinterpret_cast<const float4*>(x + (size_t)col * DIN)[lane];
    float* dst = g_z + (size_t)row * DIN + lane * 4;
    atomicAdd(dst + 0, w * xv.x);
    atomicAdd(dst + 1, w * xv.y);
    atomicAdd(dst + 2, w * xv.z);
    atomicAdd(dst + 3, w * xv.w);
}

// ---------------------------------------------------------------------------
// Kernel 4: out = relu(z_mix @ W^T + b). Classic 64x64 register-tiled SGEMM.
// M = 50000, N = 128, K = 128. Block = 256 threads, 4x4 microtile per thread.
// ---------------------------------------------------------------------------
#define BM 64
#define BN 64
#define BK 16

__global__ void gemm_relu_kernel(const float* __restrict__ W,
                                 const float* __restrict__ bias,
                                 float* __restrict__ out) {
    __shared__ float As[BK][BM + 1];  // As[k][m] = z[m0+m][k0+k]  (+1 pad: conflict-free stores)
    __shared__ float Bs[BK][BN + 1];  // Bs[k][n] = W[n0+n][k0+k]

    const int tid = threadIdx.x;       // 0..255
    const int tx  = tid & 15;          // output-col group
    const int ty  = tid >> 4;          // output-row group
    const int m0  = blockIdx.x * BM;
    const int n0  = blockIdx.y * BN;

    float acc[4][4];
    #pragma unroll
    for (int i = 0; i < 4; i++)
        #pragma unroll
        for (int j = 0; j < 4; j++) acc[i][j] = 0.f;

    const int lrow = tid >> 2;         // 0..63
    const int lkq  = (tid & 3) * 4;    // 0,4,8,12

    for (int k0 = 0; k0 < DIN; k0 += BK) {
        // Load z tile (guard M edge)
        {
            int gm = m0 + lrow;
            float4 v = make_float4(0.f, 0.f, 0.f, 0.f);
            if (gm < NNODES)
                v = reinterpret_cast<const float4*>(g_z + (size_t)gm * DIN + k0 + lkq)[0];
            As[lkq + 0][lrow] = v.x; As[lkq + 1][lrow] = v.y;
            As[lkq + 2][lrow] = v.z; As[lkq + 3][lrow] = v.w;
        }
        // Load W tile
        {
            float4 v = reinterpret_cast<const float4*>(
                W + (size_t)(n0 + lrow) * DIN + k0 + lkq)[0];
            Bs[lkq + 0][lrow] = v.x; Bs[lkq + 1][lrow] = v.y;
            Bs[lkq + 2][lrow] = v.z; Bs[lkq + 3][lrow] = v.w;
        }
        __syncthreads();

        #pragma unroll
        for (int kk = 0; kk < BK; kk++) {
            float a[4], bb[4];
            #pragma unroll
            for (int i = 0; i < 4; i++) a[i]  = As[kk][ty * 4 + i];
            #pragma unroll
            for (int j = 0; j < 4; j++) bb[j] = Bs[kk][tx * 4 + j];
            #pragma unroll
            for (int i = 0; i < 4; i++)
                #pragma unroll
                for (int j = 0; j < 4; j++)
                    acc[i][j] = fmaf(a[i], bb[j], acc[i][j]);
        }
        __syncthreads();
    }

    #pragma unroll
    for (int i = 0; i < 4; i++) {
        int gm = m0 + ty * 4 + i;
        if (gm >= NNODES) continue;
        #pragma unroll
        for (int j = 0; j < 4; j++) {
            int gn = n0 + tx * 4 + j;
            float v = acc[i][j] + bias[gn];
            out[(size_t)gm * DOUT + gn] = v > 0.f ? v : 0.f;
        }
    }
}

// ---------------------------------------------------------------------------
// Launch
// Inputs (metadata order): x, lp_rows, lp_cols, lp_vals, hp_rows, hp_cols,
//                          hp_vals, alpha_w, alpha_b, W, b
// Output: [out (N*DOUT floats)] then [alpha (N floats)]
// ---------------------------------------------------------------------------
extern "C" void kernel_launch(void* const* d_in, const int* in_sizes, int n_in,
                              void* d_out, int out_size) {
    const float* x   = (const float*)d_in[0];
    const int*   lpr = (const int*)  d_in[1];
    const int*   lpc = (const int*)  d_in[2];
    const float* lpv = (const float*)d_in[3];
    const int*   hpr = (const int*)  d_in[4];
    const int*   hpc = (const int*)  d_in[5];
    const float* hpv = (const float*)d_in[6];
    const float* aw  = (const float*)d_in[7];
    const float* ab  = (const float*)d_in[8];
    const float* W   = (const float*)d_in[9];
    const float* b   = (const float*)d_in[10];

    float* out       = (float*)d_out;
    float* alpha_out = (float*)d_out + (out_size - NNODES);

    // 1) zero z_mix
    {
        int total4 = NNODES * DIN / 4;
        int threads = 256;
        int blocks = (total4 + threads - 1) / threads;
        zero_z_kernel<<<blocks, threads>>>();
    }
    // 2) alpha (one warp per node)
    {
        int threads = 256;                      // 8 warps/block
        int blocks = (NNODES + 7) / 8;
        alpha_kernel<<<blocks, threads>>>(x, aw, ab, alpha_out);
    }
    // 3) fused gated scatter (one warp per edge-slot, 2E slots)
    {
        int threads = 256;                      // 8 warps/block
        int blocks = (2 * NEDGES + 7) / 8;
        scatter_kernel<<<blocks, threads>>>(x, lpr, lpc, lpv, hpr, hpc, hpv);
    }
    // 4) GEMM + bias + relu
    {
        dim3 grid((NNODES + BM - 1) / BM, DOUT / BN);
        gemm_relu_kernel<<<grid, 256>>>(W, b, out);
    }
}

// round 8
// speedup vs baseline: 2.1172x; 2.1172x over previous
#include <cuda_runtime.h>
#include <math.h>

// Problem constants (from reference)
#define NNODES 50000
#define NEDGES 800000
#define DIN    128
#define DOUT   128
#define NTOT   (2 * NEDGES)

// Scratch (static device arrays — no allocation allowed)
__device__ float g_z[(size_t)NNODES * DIN];     // 25.6 MB mixed aggregation buffer
__device__ float g_alpha[NNODES];
__device__ int   g_cnt[NNODES];                 // histogram
__device__ int   g_start[NNODES + 1];           // CSR row starts (exclusive scan)
__device__ int   g_cur[NNODES];                 // placement cursors
__device__ int   g_ecol[NTOT];                  // packed col | (is_lp<<30)
__device__ float g_eval[NTOT];                  // edge values

// ---------------------------------------------------------------------------
// Kernel: zero the histogram
// ---------------------------------------------------------------------------
__global__ void zero_cnt_kernel() {
    int i = blockIdx.x * blockDim.x + threadIdx.x;
    if (i < NNODES) g_cnt[i] = 0;
}

// ---------------------------------------------------------------------------
// Kernel: per-node gate alpha = sigmoid(x_i . theta + b). One warp per node.
// ---------------------------------------------------------------------------
__global__ void alpha_kernel(const float* __restrict__ x,
                             const float* __restrict__ aw,
                             const float* __restrict__ ab,
                             float* __restrict__ alpha_out) {
    int warp = (blockIdx.x * blockDim.x + threadIdx.x) >> 5;
    int lane = threadIdx.x & 31;
    if (warp >= NNODES) return;
    float4 xv = reinterpret_cast<const float4*>(x + (size_t)warp * DIN)[lane];
    float4 wv = reinterpret_cast<const float4*>(aw)[lane];
    float s = xv.x * wv.x + xv.y * wv.y + xv.z * wv.z + xv.w * wv.w;
    #pragma unroll
    for (int o = 16; o > 0; o >>= 1) s += __shfl_xor_sync(0xffffffffu, s, o);
    if (lane == 0) {
        float a = 1.0f / (1.0f + expf(-(s + ab[0])));
        g_alpha[warp]   = a;
        alpha_out[warp] = a;
    }
}

// ---------------------------------------------------------------------------
// Kernel: histogram of destination rows over the combined lp+hp edge stream
// ---------------------------------------------------------------------------
__global__ void hist_kernel(const int* __restrict__ lpr,
                            const int* __restrict__ hpr) {
    int i = blockIdx.x * blockDim.x + threadIdx.x;
    if (i < NEDGES)      atomicAdd(&g_cnt[lpr[i]], 1);
    else if (i < NTOT)   atomicAdd(&g_cnt[hpr[i - NEDGES]], 1);
}

// ---------------------------------------------------------------------------
// Kernel: single-block exclusive scan of g_cnt -> g_start, g_cur
// 1024 threads, each owns a contiguous chunk of ceil(N/1024)=49 rows.
// ---------------------------------------------------------------------------
__global__ void scan_kernel() {
    const int T = 1024;
    const int C = (NNODES + T - 1) / T;   // 49
    int t = threadIdx.x;
    int base = t * C;

    // pass 1: chunk sum
    int s = 0;
    for (int j = 0; j < C; j++) {
        int idx = base + j;
        if (idx < NNODES) s += g_cnt[idx];
    }

    // inclusive scan of per-thread sums
    int lane = t & 31, wid = t >> 5;
    int v = s;
    #pragma unroll
    for (int o = 1; o < 32; o <<= 1) {
        int n = __shfl_up_sync(0xffffffffu, v, o);
        if (lane >= o) v += n;
    }
    __shared__ int ws[32];
    if (lane == 31) ws[wid] = v;
    __syncthreads();
    if (wid == 0) {
        int u = ws[lane];
        #pragma unroll
        for (int o = 1; o < 32; o <<= 1) {
            int n = __shfl_up_sync(0xffffffffu, u, o);
            if (lane >= o) u += n;
        }
        ws[lane] = u;
    }
    __syncthreads();

    int off = (v - s) + (wid > 0 ? ws[wid - 1] : 0);  // exclusive prefix of chunk

    // pass 2: write row starts + cursors
    for (int j = 0; j < C; j++) {
        int idx = base + j;
        if (idx < NNODES) {
            int c = g_cnt[idx];
            g_start[idx] = off;
            g_cur[idx]   = off;
            off += c;
        } else if (idx == NNODES) {
            g_start[NNODES] = off;  // == NTOT
        }
    }
}

// ---------------------------------------------------------------------------
// Kernel: place edges into CSR slots (order within a row is arbitrary; fp
// summation order noise is ~1e-7, far under the 1e-3 threshold)
// ---------------------------------------------------------------------------
__global__ void place_kernel(const int* __restrict__ lpr, const int* __restrict__ lpc,
                             const float* __restrict__ lpv,
                             const int* __restrict__ hpr, const int* __restrict__ hpc,
                             const float* __restrict__ hpv) {
    int i = blockIdx.x * blockDim.x + threadIdx.x;
    if (i >= NTOT) return;
    int row, col, flag;
    float val;
    if (i < NEDGES) {
        row = lpr[i]; col = lpc[i]; val = lpv[i]; flag = 1;
    } else {
        int e = i - NEDGES;
        row = hpr[e]; col = hpc[e]; val = hpv[e]; flag = 0;
    }
    int pos = atomicAdd(&g_cur[row], 1);
    g_ecol[pos] = col | (flag << 30);
    g_eval[pos] = val;
}

// ---------------------------------------------------------------------------
// Kernel: atomic-free aggregate. One warp per destination row; each lane owns
// 4 features. Gathers x[col] for every edge of the row, applies the gate-
// folded weight, accumulates in registers, stores z_mix[row] once.
// Unrolled by 2 for memory-level parallelism.
// ---------------------------------------------------------------------------
__global__ void aggregate_kernel(const float* __restrict__ x) {
    int warp = (blockIdx.x * blockDim.x + threadIdx.x) >> 5;
    int lane = threadIdx.x & 31;
    if (warp >= NNODES) return;

    int s = g_start[warp];
    int e = g_start[warp + 1];
    float a  = g_alpha[warp];
    float ia = 1.0f - a;

    float4 acc = make_float4(0.f, 0.f, 0.f, 0.f);

    int i = s;
    for (; i + 1 < e; i += 2) {
        int   c0 = g_ecol[i],     c1 = g_ecol[i + 1];
        float v0 = g_eval[i],     v1 = g_eval[i + 1];
        int col0 = c0 & 0x3FFFFFFF, col1 = c1 & 0x3FFFFFFF;
        float w0 = (c0 & 0x40000000) ? a * v0 : ia * v0;
        float w1 = (c1 & 0x40000000) ? a * v1 : ia * v1;
        float4 x0 = reinterpret_cast<const float4*>(x + (size_t)col0 * DIN)[lane];
        float4 x1 = reinterpret_cast<const float4*>(x + (size_t)col1 * DIN)[lane];
        acc.x = fmaf(w0, x0.x, acc.x); acc.y = fmaf(w0, x0.y, acc.y);
        acc.z = fmaf(w0, x0.z, acc.z); acc.w = fmaf(w0, x0.w, acc.w);
        acc.x = fmaf(w1, x1.x, acc.x); acc.y = fmaf(w1, x1.y, acc.y);
        acc.z = fmaf(w1, x1.z, acc.z); acc.w = fmaf(w1, x1.w, acc.w);
    }
    if (i < e) {
        int   c0 = g_ecol[i];
        float v0 = g_eval[i];
        int col0 = c0 & 0x3FFFFFFF;
        float w0 = (c0 & 0x40000000) ? a * v0 : ia * v0;
        float4 x0 = reinterpret_cast<const float4*>(x + (size_t)col0 * DIN)[lane];
        acc.x = fmaf(w0, x0.x, acc.x); acc.y = fmaf(w0, x0.y, acc.y);
        acc.z = fmaf(w0, x0.z, acc.z); acc.w = fmaf(w0, x0.w, acc.w);
    }

    reinterpret_cast<float4*>(g_z + (size_t)warp * DIN)[lane] = acc;
}

// ---------------------------------------------------------------------------
// Kernel: out = relu(z_mix @ W^T + b). 64x64 register-tiled SGEMM (unchanged).
// ---------------------------------------------------------------------------
#define BM 64
#define BN 64
#define BK 16

__global__ void gemm_relu_kernel(const float* __restrict__ W,
                                 const float* __restrict__ bias,
                                 float* __restrict__ out) {
    __shared__ float As[BK][BM + 1];
    __shared__ float Bs[BK][BN + 1];

    const int tid = threadIdx.x;
    const int tx  = tid & 15;
    const int ty  = tid >> 4;
    const int m0  = blockIdx.x * BM;
    const int n0  = blockIdx.y * BN;

    float acc[4][4];
    #pragma unroll
    for (int i = 0; i < 4; i++)
        #pragma unroll
        for (int j = 0; j < 4; j++) acc[i][j] = 0.f;

    const int lrow = tid >> 2;
    const int lkq  = (tid & 3) * 4;

    for (int k0 = 0; k0 < DIN; k0 += BK) {
        {
            int gm = m0 + lrow;
            float4 v = make_float4(0.f, 0.f, 0.f, 0.f);
            if (gm < NNODES)
                v = reinterpret_cast<const float4*>(g_z + (size_t)gm * DIN + k0 + lkq)[0];
            As[lkq + 0][lrow] = v.x; As[lkq + 1][lrow] = v.y;
            As[lkq + 2][lrow] = v.z; As[lkq + 3][lrow] = v.w;
        }
        {
            float4 v = reinterpret_cast<const float4*>(
                W + (size_t)(n0 + lrow) * DIN + k0 + lkq)[0];
            Bs[lkq + 0][lrow] = v.x; Bs[lkq + 1][lrow] = v.y;
            Bs[lkq + 2][lrow] = v.z; Bs[lkq + 3][lrow] = v.w;
        }
        __syncthreads();

        #pragma unroll
        for (int kk = 0; kk < BK; kk++) {
            float a[4], bb[4];
            #pragma unroll
            for (int i = 0; i < 4; i++) a[i]  = As[kk][ty * 4 + i];
            #pragma unroll
            for (int j = 0; j < 4; j++) bb[j] = Bs[kk][tx * 4 + j];
            #pragma unroll
            for (int i = 0; i < 4; i++)
                #pragma unroll
                for (int j = 0; j < 4; j++)
                    acc[i][j] = fmaf(a[i], bb[j], acc[i][j]);
        }
        __syncthreads();
    }

    #pragma unroll
    for (int i = 0; i < 4; i++) {
        int gm = m0 + ty * 4 + i;
        if (gm >= NNODES) continue;
        #pragma unroll
        for (int j = 0; j < 4; j++) {
            int gn = n0 + tx * 4 + j;
            float v = acc[i][j] + bias[gn];
            out[(size_t)gm * DOUT + gn] = v > 0.f ? v : 0.f;
        }
    }
}

// ---------------------------------------------------------------------------
// Launch
// Inputs: x, lp_rows, lp_cols, lp_vals, hp_rows, hp_cols, hp_vals,
//         alpha_w, alpha_b, W, b
// Output: [out (N*DOUT floats)] then [alpha (N floats)]
// ---------------------------------------------------------------------------
extern "C" void kernel_launch(void* const* d_in, const int* in_sizes, int n_in,
                              void* d_out, int out_size) {
    const float* x   = (const float*)d_in[0];
    const int*   lpr = (const int*)  d_in[1];
    const int*   lpc = (const int*)  d_in[2];
    const float* lpv = (const float*)d_in[3];
    const int*   hpr = (const int*)  d_in[4];
    const int*   hpc = (const int*)  d_in[5];
    const float* hpv = (const float*)d_in[6];
    const float* aw  = (const float*)d_in[7];
    const float* ab  = (const float*)d_in[8];
    const float* W   = (const float*)d_in[9];
    const float* b   = (const float*)d_in[10];

    float* out       = (float*)d_out;
    float* alpha_out = (float*)d_out + (out_size - NNODES);

    // 1) zero histogram
    zero_cnt_kernel<<<(NNODES + 255) / 256, 256>>>();

    // 2) alpha gate (one warp per node)
    alpha_kernel<<<(NNODES + 7) / 8, 256>>>(x, aw, ab, alpha_out);

    // 3) histogram of destination rows
    hist_kernel<<<(NTOT + 255) / 256, 256>>>(lpr, hpr);

    // 4) exclusive scan -> CSR row starts + cursors
    scan_kernel<<<1, 1024>>>();

    // 5) place edges into CSR slots
    place_kernel<<<(NTOT + 255) / 256, 256>>>(lpr, lpc, lpv, hpr, hpc, hpv);

    // 6) atomic-free gather-aggregate (one warp per row)
    aggregate_kernel<<<(NNODES + 7) / 8, 256>>>(x);

    // 7) GEMM + bias + relu
    {
        dim3 grid((NNODES + BM - 1) / BM, DOUT / BN);
        gemm_relu_kernel<<<grid, 256>>>(W, b, out);
    }
}

// round 11
// speedup vs baseline: 3.1346x; 1.4806x over previous
#include <cuda_runtime.h>
#include <math.h>

// Problem constants (from reference)
#define NNODES 50000
#define NEDGES 800000
#define DIN    128
#define DOUT   128
#define NTOT   (2 * NEDGES)
#define NB_SCAN ((NNODES + 255) / 256)   // 196 scan blocks

// Scratch (static device arrays — no allocation allowed)
__device__ float g_z[(size_t)NNODES * DIN];     // 25.6 MB mixed aggregation buffer
__device__ float g_alpha[NNODES];
__device__ int   g_cnt[NNODES];                 // histogram
__device__ int   g_start[NNODES + 1];           // CSR row starts (exclusive scan)
__device__ int   g_cur[NNODES];                 // placement cursors
__device__ int   g_ecol[NTOT];                  // packed col | (is_lp<<30)
__device__ float g_eval[NTOT];                  // edge values
__device__ int   g_bsum[NB_SCAN];               // per-block partial sums
__device__ int   g_boff[NB_SCAN];               // per-block exclusive offsets

// ---------------------------------------------------------------------------
// Kernel: zero the histogram
// ---------------------------------------------------------------------------
__global__ void zero_cnt_kernel() {
    int i = blockIdx.x * blockDim.x + threadIdx.x;
    if (i < NNODES) g_cnt[i] = 0;
}

// ---------------------------------------------------------------------------
// Kernel: per-node gate alpha = sigmoid(x_i . theta + b). One warp per node.
// ---------------------------------------------------------------------------
__global__ void alpha_kernel(const float* __restrict__ x,
                             const float* __restrict__ aw,
                             const float* __restrict__ ab,
                             float* __restrict__ alpha_out) {
    int warp = (blockIdx.x * blockDim.x + threadIdx.x) >> 5;
    int lane = threadIdx.x & 31;
    if (warp >= NNODES) return;
    float4 xv = reinterpret_cast<const float4*>(x + (size_t)warp * DIN)[lane];
    float4 wv = reinterpret_cast<const float4*>(aw)[lane];
    float s = xv.x * wv.x + xv.y * wv.y + xv.z * wv.z + xv.w * wv.w;
    #pragma unroll
    for (int o = 16; o > 0; o >>= 1) s += __shfl_xor_sync(0xffffffffu, s, o);
    if (lane == 0) {
        float a = 1.0f / (1.0f + expf(-(s + ab[0])));
        g_alpha[warp]   = a;
        alpha_out[warp] = a;
    }
}

// ---------------------------------------------------------------------------
// Kernel: histogram of destination rows over the combined lp+hp edge stream
// ---------------------------------------------------------------------------
__global__ void hist_kernel(const int* __restrict__ lpr,
                            const int* __restrict__ hpr) {
    int i = blockIdx.x * blockDim.x + threadIdx.x;
    if (i < NEDGES)      atomicAdd(&g_cnt[lpr[i]], 1);
    else if (i < NTOT)   atomicAdd(&g_cnt[hpr[i - NEDGES]], 1);
}

// ---------------------------------------------------------------------------
// 3-phase full-chip exclusive scan of g_cnt (50000 ints)
// Phase A: per-block (256-elem) sums -> g_bsum
// Phase B: single tiny block scans 196 partials -> g_boff (exclusive)
// Phase C: per-block re-scan + offset -> g_start, g_cur
// ---------------------------------------------------------------------------
__global__ void scan_a_kernel() {
    int idx = blockIdx.x * 256 + threadIdx.x;
    int c = (idx < NNODES) ? g_cnt[idx] : 0;
    int lane = threadIdx.x & 31, wid = threadIdx.x >> 5;
    #pragma unroll
    for (int o = 16; o > 0; o >>= 1) c += __shfl_xor_sync(0xffffffffu, c, o);
    __shared__ int ws[8];
    if (lane == 0) ws[wid] = c;
    __syncthreads();
    if (threadIdx.x == 0) {
        int s = 0;
        #pragma unroll
        for (int w = 0; w < 8; w++) s += ws[w];
        g_bsum[blockIdx.x] = s;
    }
}

__global__ void scan_b_kernel() {
    int t = threadIdx.x;                 // 256 threads, NB_SCAN=196 live
    int c = (t < NB_SCAN) ? g_bsum[t] : 0;
    int lane = t & 31, wid = t >> 5;
    int v = c;
    #pragma unroll
    for (int o = 1; o < 32; o <<= 1) {
        int n = __shfl_up_sync(0xffffffffu, v, o);
        if (lane >= o) v += n;
    }
    __shared__ int ws[8];
    if (lane == 31) ws[wid] = v;
    __syncthreads();
    if (wid == 0 && lane < 8) {
        int u = ws[lane];
        #pragma unroll
        for (int o = 1; o < 8; o <<= 1) {
            int n = __shfl_up_sync(0x000000ffu, u, o);
            if (lane >= o) u += n;
        }
        ws[lane] = u;
    }
    __syncthreads();
    int incl = v + (wid > 0 ? ws[wid - 1] : 0);
    if (t < NB_SCAN) g_boff[t] = incl - c;   // exclusive
}

__global__ void scan_c_kernel() {
    int b = blockIdx.x, t = threadIdx.x;
    int idx = b * 256 + t;
    int c = (idx < NNODES) ? g_cnt[idx] : 0;
    int lane = t & 31, wid = t >> 5;
    int v = c;
    #pragma unroll
    for (int o = 1; o < 32; o <<= 1) {
        int n = __shfl_up_sync(0xffffffffu, v, o);
        if (lane >= o) v += n;
    }
    __shared__ int ws[8];
    if (lane == 31) ws[wid] = v;
    __syncthreads();
    if (wid == 0 && lane < 8) {
        int u = ws[lane];
        #pragma unroll
        for (int o = 1; o < 8; o <<= 1) {
            int n = __shfl_up_sync(0x000000ffu, u, o);
            if (lane >= o) u += n;
        }
        ws[lane] = u;
    }
    __syncthreads();
    int excl = (v - c) + (wid > 0 ? ws[wid - 1] : 0) + g_boff[b];
    if (idx < NNODES) {
        g_start[idx] = excl;
        g_cur[idx]   = excl;
    }
    if (b == 0 && t == 0) g_start[NNODES] = NTOT;  // total edge count is constant
}

// ---------------------------------------------------------------------------
// Kernel: place edges into CSR slots
// ---------------------------------------------------------------------------
__global__ void place_kernel(const int* __restrict__ lpr, const int* __restrict__ lpc,
                             const float* __restrict__ lpv,
                             const int* __restrict__ hpr, const int* __restrict__ hpc,
                             const float* __restrict__ hpv) {
    int i = blockIdx.x * blockDim.x + threadIdx.x;
    if (i >= NTOT) return;
    int row, col, flag;
    float val;
    if (i < NEDGES) {
        row = lpr[i]; col = lpc[i]; val = lpv[i]; flag = 1;
    } else {
        int e = i - NEDGES;
        row = hpr[e]; col = hpc[e]; val = hpv[e]; flag = 0;
    }
    int pos = atomicAdd(&g_cur[row], 1);
    g_ecol[pos] = col | (flag << 30);
    g_eval[pos] = val;
}

// ---------------------------------------------------------------------------
// Kernel: atomic-free aggregate. One warp per destination row; lane owns 4
// features. 2-deep unroll for MLP.
// ---------------------------------------------------------------------------
__global__ void aggregate_kernel(const float* __restrict__ x) {
    int warp = (blockIdx.x * blockDim.x + threadIdx.x) >> 5;
    int lane = threadIdx.x & 31;
    if (warp >= NNODES) return;

    int s = g_start[warp];
    int e = g_start[warp + 1];
    float a  = g_alpha[warp];
    float ia = 1.0f - a;

    float4 acc = make_float4(0.f, 0.f, 0.f, 0.f);

    int i = s;
    for (; i + 1 < e; i += 2) {
        int   c0 = g_ecol[i],     c1 = g_ecol[i + 1];
        float v0 = g_eval[i],     v1 = g_eval[i + 1];
        int col0 = c0 & 0x3FFFFFFF, col1 = c1 & 0x3FFFFFFF;
        float w0 = (c0 & 0x40000000) ? a * v0 : ia * v0;
        float w1 = (c1 & 0x40000000) ? a * v1 : ia * v1;
        float4 x0 = reinterpret_cast<const float4*>(x + (size_t)col0 * DIN)[lane];
        float4 x1 = reinterpret_cast<const float4*>(x + (size_t)col1 * DIN)[lane];
        acc.x = fmaf(w0, x0.x, acc.x); acc.y = fmaf(w0, x0.y, acc.y);
        acc.z = fmaf(w0, x0.z, acc.z); acc.w = fmaf(w0, x0.w, acc.w);
        acc.x = fmaf(w1, x1.x, acc.x); acc.y = fmaf(w1, x1.y, acc.y);
        acc.z = fmaf(w1, x1.z, acc.z); acc.w = fmaf(w1, x1.w, acc.w);
    }
    if (i < e) {
        int   c0 = g_ecol[i];
        float v0 = g_eval[i];
        int col0 = c0 & 0x3FFFFFFF;
        float w0 = (c0 & 0x40000000) ? a * v0 : ia * v0;
        float4 x0 = reinterpret_cast<const float4*>(x + (size_t)col0 * DIN)[lane];
        acc.x = fmaf(w0, x0.x, acc.x); acc.y = fmaf(w0, x0.y, acc.y);
        acc.z = fmaf(w0, x0.z, acc.z); acc.w = fmaf(w0, x0.w, acc.w);
    }

    reinterpret_cast<float4*>(g_z + (size_t)warp * DIN)[lane] = acc;
}

// ---------------------------------------------------------------------------
// Kernel: out = relu(z_mix @ W^T + b). 128x128x8 SGEMM, 8x8 microtile,
// 256 threads. N = K = 128 so grid.y = 1 and the full W row-panel is tiled.
// ---------------------------------------------------------------------------
#define GBM 128
#define GBK 8
#define LDS_PAD 132   // 128 + 4, keeps float4 alignment (132*4 % 16 == 0)

__global__ void gemm_relu_kernel(const float* __restrict__ W,
                                 const float* __restrict__ bias,
                                 float* __restrict__ out) {
    __shared__ float As[GBK][LDS_PAD];  // As[k][m]
    __shared__ float Bs[GBK][LDS_PAD];  // Bs[k][n] = W[n][k]

    const int tid = threadIdx.x;        // 0..255
    const int tx  = tid & 15;           // n-group: 16 groups of 8 cols
    const int ty  = tid >> 4;           // m-group: 16 groups of 8 rows
    const int m0  = blockIdx.x * GBM;

    const int lrow = tid >> 1;          // 0..127 (staging row)
    const int lkq  = (tid & 1) * 4;     // 0 or 4 (staging k quad)

    float acc[8][8];
    #pragma unroll
    for (int i = 0; i < 8; i++)
        #pragma unroll
        for (int j = 0; j < 8; j++) acc[i][j] = 0.f;

    for (int k0 = 0; k0 < DIN; k0 += GBK) {
        // Stage A tile: z[m0+lrow][k0+lkq..+4]
        {
            int gm = m0 + lrow;
            float4 v = make_float4(0.f, 0.f, 0.f, 0.f);
            if (gm < NNODES)
                v = reinterpret_cast<const float4*>(g_z + (size_t)gm * DIN + k0 + lkq)[0];
            As[lkq + 0][lrow] = v.x; As[lkq + 1][lrow] = v.y;
            As[lkq + 2][lrow] = v.z; As[lkq + 3][lrow] = v.w;
        }
        // Stage B tile: W[lrow][k0+lkq..+4]  (Bs[k][n] transposed store)
        {
            float4 v = reinterpret_cast<const float4*>(
                W + (size_t)lrow * DIN + k0 + lkq)[0];
            Bs[lkq + 0][lrow] = v.x; Bs[lkq + 1][lrow] = v.y;
            Bs[lkq + 2][lrow] = v.z; Bs[lkq + 3][lrow] = v.w;
        }
        __syncthreads();

        #pragma unroll
        for (int kk = 0; kk < GBK; kk++) {
            float a[8], bb[8];
            float4 a0 = reinterpret_cast<const float4*>(&As[kk][ty * 8])[0];
            float4 a1 = reinterpret_cast<const float4*>(&As[kk][ty * 8])[1];
            float4 b0 = reinterpret_cast<const float4*>(&Bs[kk][tx * 8])[0];
            float4 b1 = reinterpret_cast<const float4*>(&Bs[kk][tx * 8])[1];
            a[0]=a0.x; a[1]=a0.y; a[2]=a0.z; a[3]=a0.w;
            a[4]=a1.x; a[5]=a1.y; a[6]=a1.z; a[7]=a1.w;
            bb[0]=b0.x; bb[1]=b0.y; bb[2]=b0.z; bb[3]=b0.w;
            bb[4]=b1.x; bb[5]=b1.y; bb[6]=b1.z; bb[7]=b1.w;
            #pragma unroll
            for (int i = 0; i < 8; i++)
                #pragma unroll
                for (int j = 0; j < 8; j++)
                    acc[i][j] = fmaf(a[i], bb[j], acc[i][j]);
        }
        __syncthreads();
    }

    #pragma unroll
    for (int i = 0; i < 8; i++) {
        int gm = m0 + ty * 8 + i;
        if (gm >= NNODES) continue;
        #pragma unroll
        for (int j = 0; j < 8; j += 4) {
            int gn = tx * 8 + j;
            float4 v;
            v.x = acc[i][j + 0] + bias[gn + 0];
            v.y = acc[i][j + 1] + bias[gn + 1];
            v.z = acc[i][j + 2] + bias[gn + 2];
            v.w = acc[i][j + 3] + bias[gn + 3];
            v.x = v.x > 0.f ? v.x : 0.f;
            v.y = v.y > 0.f ? v.y : 0.f;
            v.z = v.z > 0.f ? v.z : 0.f;
            v.w = v.w > 0.f ? v.w : 0.f;
            reinterpret_cast<float4*>(out + (size_t)gm * DOUT + gn)[0] = v;
        }
    }
}

// ---------------------------------------------------------------------------
// Launch
// Inputs: x, lp_rows, lp_cols, lp_vals, hp_rows, hp_cols, hp_vals,
//         alpha_w, alpha_b, W, b
// Output: [out (N*DOUT floats)] then [alpha (N floats)]
// ---------------------------------------------------------------------------
extern "C" void kernel_launch(void* const* d_in, const int* in_sizes, int n_in,
                              void* d_out, int out_size) {
    const float* x   = (const float*)d_in[0];
    const int*   lpr = (const int*)  d_in[1];
    const int*   lpc = (const int*)  d_in[2];
    const float* lpv = (const float*)d_in[3];
    const int*   hpr = (const int*)  d_in[4];
    const int*   hpc = (const int*)  d_in[5];
    const float* hpv = (const float*)d_in[6];
    const float* aw  = (const float*)d_in[7];
    const float* ab  = (const float*)d_in[8];
    const float* W   = (const float*)d_in[9];
    const float* b   = (const float*)d_in[10];

    float* out       = (float*)d_out;
    float* alpha_out = (float*)d_out + (out_size - NNODES);

    // 1) zero histogram
    zero_cnt_kernel<<<(NNODES + 255) / 256, 256>>>();

    // 2) alpha gate (one warp per node)
    alpha_kernel<<<(NNODES + 7) / 8, 256>>>(x, aw, ab, alpha_out);

    // 3) histogram of destination rows
    hist_kernel<<<(NTOT + 255) / 256, 256>>>(lpr, hpr);

    // 4) 3-phase exclusive scan -> CSR row starts + cursors
    scan_a_kernel<<<NB_SCAN, 256>>>();
    scan_b_kernel<<<1, 256>>>();
    scan_c_kernel<<<NB_SCAN, 256>>>();

    // 5) place edges into CSR slots
    place_kernel<<<(NTOT + 255) / 256, 256>>>(lpr, lpc, lpv, hpr, hpc, hpv);

    // 6) atomic-free gather-aggregate (one warp per row)
    aggregate_kernel<<<(NNODES + 7) / 8, 256>>>(x);

    // 7) GEMM + bias + relu (128x128x8, 8x8 microtile)
    gemm_relu_kernel<<<(NNODES + GBM - 1) / GBM, 256>>>(W, b, out);
}

// round 12
// speedup vs baseline: 3.1896x; 1.0176x over previous
#include <cuda_runtime.h>
#include <math.h>

// Problem constants (from reference)
#define NNODES 50000
#define NEDGES 800000
#define DIN    128
#define DOUT   128
#define NTOT   (2 * NEDGES)
#define NB_SCAN ((NNODES + 255) / 256)   // 196 scan blocks

// Scratch (static device arrays — no allocation allowed)
__device__ float g_z[(size_t)NNODES * DIN];     // 25.6 MB mixed aggregation buffer
__device__ float g_alpha[NNODES];
__device__ int   g_cnt[NNODES];                 // histogram
__device__ int   g_start[NNODES + 1];           // CSR row starts (exclusive scan)
__device__ int   g_cur[NNODES];                 // placement cursors
__device__ int2  g_edge[NTOT];                  // {col | (is_lp<<30), f32_bits(val)}
__device__ int   g_bsum[NB_SCAN];               // per-block partial sums
__device__ int   g_boff[NB_SCAN];               // per-block exclusive offsets

// ---------------------------------------------------------------------------
// Kernel: zero the histogram
// ---------------------------------------------------------------------------
__global__ void zero_cnt_kernel() {
    int i = blockIdx.x * blockDim.x + threadIdx.x;
    if (i < NNODES) g_cnt[i] = 0;
}

// ---------------------------------------------------------------------------
// Kernel: per-node gate alpha = sigmoid(x_i . theta + b). One warp per node.
// ---------------------------------------------------------------------------
__global__ void alpha_kernel(const float* __restrict__ x,
                             const float* __restrict__ aw,
                             const float* __restrict__ ab,
                             float* __restrict__ alpha_out) {
    int warp = (blockIdx.x * blockDim.x + threadIdx.x) >> 5;
    int lane = threadIdx.x & 31;
    if (warp >= NNODES) return;
    float4 xv = reinterpret_cast<const float4*>(x + (size_t)warp * DIN)[lane];
    float4 wv = reinterpret_cast<const float4*>(aw)[lane];
    float s = xv.x * wv.x + xv.y * wv.y + xv.z * wv.z + xv.w * wv.w;
    #pragma unroll
    for (int o = 16; o > 0; o >>= 1) s += __shfl_xor_sync(0xffffffffu, s, o);
    if (lane == 0) {
        float a = 1.0f / (1.0f + expf(-(s + ab[0])));
        g_alpha[warp]   = a;
        alpha_out[warp] = a;
    }
}

// ---------------------------------------------------------------------------
// Kernel: histogram of destination rows over the combined lp+hp edge stream
// ---------------------------------------------------------------------------
__global__ void hist_kernel(const int* __restrict__ lpr,
                            const int* __restrict__ hpr) {
    int i = blockIdx.x * blockDim.x + threadIdx.x;
    if (i < NEDGES)      atomicAdd(&g_cnt[lpr[i]], 1);
    else if (i < NTOT)   atomicAdd(&g_cnt[hpr[i - NEDGES]], 1);
}

// ---------------------------------------------------------------------------
// 3-phase full-chip exclusive scan of g_cnt (50000 ints)
// ---------------------------------------------------------------------------
__global__ void scan_a_kernel() {
    int idx = blockIdx.x * 256 + threadIdx.x;
    int c = (idx < NNODES) ? g_cnt[idx] : 0;
    int lane = threadIdx.x & 31, wid = threadIdx.x >> 5;
    #pragma unroll
    for (int o = 16; o > 0; o >>= 1) c += __shfl_xor_sync(0xffffffffu, c, o);
    __shared__ int ws[8];
    if (lane == 0) ws[wid] = c;
    __syncthreads();
    if (threadIdx.x == 0) {
        int s = 0;
        #pragma unroll
        for (int w = 0; w < 8; w++) s += ws[w];
        g_bsum[blockIdx.x] = s;
    }
}

__global__ void scan_b_kernel() {
    int t = threadIdx.x;                 // 256 threads, NB_SCAN=196 live
    int c = (t < NB_SCAN) ? g_bsum[t] : 0;
    int lane = t & 31, wid = t >> 5;
    int v = c;
    #pragma unroll
    for (int o = 1; o < 32; o <<= 1) {
        int n = __shfl_up_sync(0xffffffffu, v, o);
        if (lane >= o) v += n;
    }
    __shared__ int ws[8];
    if (lane == 31) ws[wid] = v;
    __syncthreads();
    if (wid == 0 && lane < 8) {
        int u = ws[lane];
        #pragma unroll
        for (int o = 1; o < 8; o <<= 1) {
            int n = __shfl_up_sync(0x000000ffu, u, o);
            if (lane >= o) u += n;
        }
        ws[lane] = u;
    }
    __syncthreads();
    int incl = v + (wid > 0 ? ws[wid - 1] : 0);
    if (t < NB_SCAN) g_boff[t] = incl - c;   // exclusive
}

__global__ void scan_c_kernel() {
    int b = blockIdx.x, t = threadIdx.x;
    int idx = b * 256 + t;
    int c = (idx < NNODES) ? g_cnt[idx] : 0;
    int lane = t & 31, wid = t >> 5;
    int v = c;
    #pragma unroll
    for (int o = 1; o < 32; o <<= 1) {
        int n = __shfl_up_sync(0xffffffffu, v, o);
        if (lane >= o) v += n;
    }
    __shared__ int ws[8];
    if (lane == 31) ws[wid] = v;
    __syncthreads();
    if (wid == 0 && lane < 8) {
        int u = ws[lane];
        #pragma unroll
        for (int o = 1; o < 8; o <<= 1) {
            int n = __shfl_up_sync(0x000000ffu, u, o);
            if (lane >= o) u += n;
        }
        ws[lane] = u;
    }
    __syncthreads();
    int excl = (v - c) + (wid > 0 ? ws[wid - 1] : 0) + g_boff[b];
    if (idx < NNODES) {
        g_start[idx] = excl;
        g_cur[idx]   = excl;
    }
    if (b == 0 && t == 0) g_start[NNODES] = NTOT;
}

// ---------------------------------------------------------------------------
// Kernel: place edges into CSR slots (packed int2: one 8B store per edge)
// ---------------------------------------------------------------------------
__global__ void place_kernel(const int* __restrict__ lpr, const int* __restrict__ lpc,
                             const float* __restrict__ lpv,
                             const int* __restrict__ hpr, const int* __restrict__ hpc,
                             const float* __restrict__ hpv) {
    int i = blockIdx.x * blockDim.x + threadIdx.x;
    if (i >= NTOT) return;
    int row, col, flag;
    float val;
    if (i < NEDGES) {
        row = lpr[i]; col = lpc[i]; val = lpv[i]; flag = 1;
    } else {
        int e = i - NEDGES;
        row = hpr[e]; col = hpc[e]; val = hpv[e]; flag = 0;
    }
    int pos = atomicAdd(&g_cur[row], 1);
    g_edge[pos] = make_int2(col | (flag << 30), __float_as_int(val));
}

// ---------------------------------------------------------------------------
// Kernel: atomic-free aggregate. One warp per destination row; lane owns 4
// features. 4-deep unroll for MLP; packed int2 edge loads (broadcast).
// ---------------------------------------------------------------------------
__device__ __forceinline__ float edge_w(int c, float v, float a, float ia) {
    return (c & 0x40000000) ? a * v : ia * v;
}

__global__ void aggregate_kernel(const float* __restrict__ x) {
    int warp = (blockIdx.x * blockDim.x + threadIdx.x) >> 5;
    int lane = threadIdx.x & 31;
    if (warp >= NNODES) return;

    int s = g_start[warp];
    int e = g_start[warp + 1];
    float a  = g_alpha[warp];
    float ia = 1.0f - a;

    float4 acc = make_float4(0.f, 0.f, 0.f, 0.f);

    int i = s;
    for (; i + 3 < e; i += 4) {
        int2 e0 = g_edge[i],     e1 = g_edge[i + 1];
        int2 e2 = g_edge[i + 2], e3 = g_edge[i + 3];
        float w0 = edge_w(e0.x, __int_as_float(e0.y), a, ia);
        float w1 = edge_w(e1.x, __int_as_float(e1.y), a, ia);
        float w2 = edge_w(e2.x, __int_as_float(e2.y), a, ia);
        float w3 = edge_w(e3.x, __int_as_float(e3.y), a, ia);
        float4 x0 = reinterpret_cast<const float4*>(x + (size_t)(e0.x & 0x3FFFFFFF) * DIN)[lane];
        float4 x1 = reinterpret_cast<const float4*>(x + (size_t)(e1.x & 0x3FFFFFFF) * DIN)[lane];
        float4 x2 = reinterpret_cast<const float4*>(x + (size_t)(e2.x & 0x3FFFFFFF) * DIN)[lane];
        float4 x3 = reinterpret_cast<const float4*>(x + (size_t)(e3.x & 0x3FFFFFFF) * DIN)[lane];
        acc.x = fmaf(w0, x0.x, acc.x); acc.y = fmaf(w0, x0.y, acc.y);
        acc.z = fmaf(w0, x0.z, acc.z); acc.w = fmaf(w0, x0.w, acc.w);
        acc.x = fmaf(w1, x1.x, acc.x); acc.y = fmaf(w1, x1.y, acc.y);
        acc.z = fmaf(w1, x1.z, acc.z); acc.w = fmaf(w1, x1.w, acc.w);
        acc.x = fmaf(w2, x2.x, acc.x); acc.y = fmaf(w2, x2.y, acc.y);
        acc.z = fmaf(w2, x2.z, acc.z); acc.w = fmaf(w2, x2.w, acc.w);
        acc.x = fmaf(w3, x3.x, acc.x); acc.y = fmaf(w3, x3.y, acc.y);
        acc.z = fmaf(w3, x3.z, acc.z); acc.w = fmaf(w3, x3.w, acc.w);
    }
    for (; i < e; i++) {
        int2 e0 = g_edge[i];
        float w0 = edge_w(e0.x, __int_as_float(e0.y), a, ia);
        float4 x0 = reinterpret_cast<const float4*>(x + (size_t)(e0.x & 0x3FFFFFFF) * DIN)[lane];
        acc.x = fmaf(w0, x0.x, acc.x); acc.y = fmaf(w0, x0.y, acc.y);
        acc.z = fmaf(w0, x0.z, acc.z); acc.w = fmaf(w0, x0.w, acc.w);
    }

    reinterpret_cast<float4*>(g_z + (size_t)warp * DIN)[lane] = acc;
}

// ---------------------------------------------------------------------------
// Kernel: out = relu(z_mix @ W^T + b). 128x128x8 SGEMM, 8x8 microtile,
// packed fma.rn.f32x2 (FFMA2) inner loop -> 2x fp32 FMA throughput.
// ---------------------------------------------------------------------------
#define GBM 128
#define GBK 8
#define LDS_PAD 132   // 128 + 4, keeps float4 alignment (132*4 % 16 == 0)

__global__ void __launch_bounds__(256)
gemm_relu_kernel(const float* __restrict__ W,
                 const float* __restrict__ bias,
                 float* __restrict__ out) {
    __shared__ float As[GBK][LDS_PAD];  // As[k][m]
    __shared__ float Bs[GBK][LDS_PAD];  // Bs[k][n] = W[n][k]

    const int tid = threadIdx.x;        // 0..255
    const int tx  = tid & 15;           // n-group: 16 groups of 8 cols
    const int ty  = tid >> 4;           // m-group: 16 groups of 8 rows
    const int m0  = blockIdx.x * GBM;

    const int lrow = tid >> 1;          // 0..127 (staging row)
    const int lkq  = (tid & 1) * 4;     // 0 or 4 (staging k quad)

    // acc[i][jp]: packed f32x2 pair (cols 2jp, 2jp+1) for row i
    unsigned long long acc[8][4];
    #pragma unroll
    for (int i = 0; i < 8; i++)
        #pragma unroll
        for (int j = 0; j < 4; j++) acc[i][j] = 0ull;

    for (int k0 = 0; k0 < DIN; k0 += GBK) {
        // Stage A tile: z[m0+lrow][k0+lkq..+4]
        {
            int gm = m0 + lrow;
            float4 v = make_float4(0.f, 0.f, 0.f, 0.f);
            if (gm < NNODES)
                v = reinterpret_cast<const float4*>(g_z + (size_t)gm * DIN + k0 + lkq)[0];
            As[lkq + 0][lrow] = v.x; As[lkq + 1][lrow] = v.y;
            As[lkq + 2][lrow] = v.z; As[lkq + 3][lrow] = v.w;
        }
        // Stage B tile: W[lrow][k0+lkq..+4]  (Bs[k][n] transposed store)
        {
            float4 v = reinterpret_cast<const float4*>(
                W + (size_t)lrow * DIN + k0 + lkq)[0];
            Bs[lkq + 0][lrow] = v.x; Bs[lkq + 1][lrow] = v.y;
            Bs[lkq + 2][lrow] = v.z; Bs[lkq + 3][lrow] = v.w;
        }
        __syncthreads();

        #pragma unroll
        for (int kk = 0; kk < GBK; kk++) {
            float a[8];
            {
                float4 a0 = reinterpret_cast<const float4*>(&As[kk][ty * 8])[0];
                float4 a1 = reinterpret_cast<const float4*>(&As[kk][ty * 8])[1];
                a[0]=a0.x; a[1]=a0.y; a[2]=a0.z; a[3]=a0.w;
                a[4]=a1.x; a[5]=a1.y; a[6]=a1.z; a[7]=a1.w;
            }
            unsigned long long bp[4];
            {
                const ulonglong2* bq = reinterpret_cast<const ulonglong2*>(&Bs[kk][tx * 8]);
                ulonglong2 q0 = bq[0], q1 = bq[1];
                bp[0] = q0.x; bp[1] = q0.y; bp[2] = q1.x; bp[3] = q1.y;
            }
            #pragma unroll
            for (int i = 0; i < 8; i++) {
                unsigned long long ap;
                asm("mov.b64 %0, {%1, %1};" : "=l"(ap) : "f"(a[i]));
                asm("fma.rn.f32x2 %0, %1, %2, %0;" : "+l"(acc[i][0]) : "l"(ap), "l"(bp[0]));
                asm("fma.rn.f32x2 %0, %1, %2, %0;" : "+l"(acc[i][1]) : "l"(ap), "l"(bp[1]));
                asm("fma.rn.f32x2 %0, %1, %2, %0;" : "+l"(acc[i][2]) : "l"(ap), "l"(bp[2]));
                asm("fma.rn.f32x2 %0, %1, %2, %0;" : "+l"(acc[i][3]) : "l"(ap), "l"(bp[3]));
            }
        }
        __syncthreads();
    }

    #pragma unroll
    for (int i = 0; i < 8; i++) {
        int gm = m0 + ty * 8 + i;
        if (gm >= NNODES) continue;
        #pragma unroll
        for (int jp = 0; jp < 4; jp += 2) {
            int gn = tx * 8 + jp * 2;
            float c0, c1, c2, c3;
            asm("mov.b64 {%0, %1}, %2;" : "=f"(c0), "=f"(c1) : "l"(acc[i][jp]));
            asm("mov.b64 {%0, %1}, %2;" : "=f"(c2), "=f"(c3) : "l"(acc[i][jp + 1]));
            float4 v;
            v.x = c0 + bias[gn + 0];
            v.y = c1 + bias[gn + 1];
            v.z = c2 + bias[gn + 2];
            v.w = c3 + bias[gn + 3];
            v.x = v.x > 0.f ? v.x : 0.f;
            v.y = v.y > 0.f ? v.y : 0.f;
            v.z = v.z > 0.f ? v.z : 0.f;
            v.w = v.w > 0.f ? v.w : 0.f;
            reinterpret_cast<float4*>(out + (size_t)gm * DOUT + gn)[0] = v;
        }
    }
}

// ---------------------------------------------------------------------------
// Launch
// Inputs: x, lp_rows, lp_cols, lp_vals, hp_rows, hp_cols, hp_vals,
//         alpha_w, alpha_b, W, b
// Output: [out (N*DOUT floats)] then [alpha (N floats)]
// ---------------------------------------------------------------------------
extern "C" void kernel_launch(void* const* d_in, const int* in_sizes, int n_in,
                              void* d_out, int out_size) {
    const float* x   = (const float*)d_in[0];
    const int*   lpr = (const int*)  d_in[1];
    const int*   lpc = (const int*)  d_in[2];
    const float* lpv = (const float*)d_in[3];
    const int*   hpr = (const int*)  d_in[4];
    const int*   hpc = (const int*)  d_in[5];
    const float* hpv = (const float*)d_in[6];
    const float* aw  = (const float*)d_in[7];
    const float* ab  = (const float*)d_in[8];
    const float* W   = (const float*)d_in[9];
    const float* b   = (const float*)d_in[10];

    float* out       = (float*)d_out;
    float* alpha_out = (float*)d_out + (out_size - NNODES);

    // 1) zero histogram
    zero_cnt_kernel<<<(NNODES + 255) / 256, 256>>>();

    // 2) alpha gate (one warp per node)
    alpha_kernel<<<(NNODES + 7) / 8, 256>>>(x, aw, ab, alpha_out);

    // 3) histogram of destination rows
    hist_kernel<<<(NTOT + 255) / 256, 256>>>(lpr, hpr);

    // 4) 3-phase exclusive scan -> CSR row starts + cursors
    scan_a_kernel<<<NB_SCAN, 256>>>();
    scan_b_kernel<<<1, 256>>>();
    scan_c_kernel<<<NB_SCAN, 256>>>();

    // 5) place edges into CSR slots (packed int2)
    place_kernel<<<(NTOT + 255) / 256, 256>>>(lpr, lpc, lpv, hpr, hpc, hpv);

    // 6) atomic-free gather-aggregate (one warp per row)
    aggregate_kernel<<<(NNODES + 7) / 8, 256>>>(x);

    // 7) GEMM + bias + relu (128x128x8, 8x8 microtile, FFMA2)
    gemm_relu_kernel<<<(NNODES + GBM - 1) / GBM, 256>>>(W, b, out);
}